// round 13
// baseline (speedup 1.0000x reference)
#include <cuda_runtime.h>
#include <math.h>

#define NB 256
typedef unsigned long long u64;

// Compact global scratch (static; no runtime allocation)
__device__ float g_vals[(size_t)2 * 256 * 128 * 12];  // [h][b][c]{ews0..7, ec, invp, invm, pad}
__device__ uint2 g_rows[256 * 128];                   // [b][c] 8 packed row bytes
__device__ float g_feats[4 * NB * 21];                // m-chains at slots (2+h)*256+b
__device__ float g_ent[2 * 256 * 36];                 // [h][b]: T^a entries (a=0..8)x{ii,ij,ji,jj}
__device__ float g_omega[NB * 2];

// ---------------- packed fp32 helpers ----------------
__device__ __forceinline__ void ffma2(u64& a, u64 x, u64 y) {
    asm("fma.rn.f32x2 %0, %1, %2, %0;" : "+l"(a) : "l"(x), "l"(y));
}
__device__ __forceinline__ float2 unpk(u64 v) {
    float lo, hi; asm("mov.b64 {%0, %1}, %2;" : "=f"(lo), "=f"(hi) : "l"(v));
    return make_float2(lo, hi);
}

// ============================================================================
// Kernel 1: per-batch GCN + attention. Pack-free m-paired f32x2 GEMMs.
// smem floats: Wt 0(1152, 32x36 transposed) X 1152(4608,str36) XW 5760(4608)
//   Q2 10368(8704,str68) K2 19072(8704) dinv 27776(128) wcs 27904(4)
//   rows8 27908(256 floats)  total 28164 floats = 112.7KB -> 2 CTA/SM
// ============================================================================
#define SMB_FLOATS 28164

// gather-transpose prefetch: thread (c = tid>>3, mq = (tid&7)*4) fetches
// W[mq..mq+3][coloff + c] from row-major gmem W
__device__ __forceinline__ float4 ldgWt(const float* __restrict__ Wg, int stride,
                                        int coloff, int tid) {
    int c = tid >> 3, mq = (tid & 7) * 4;
    return make_float4(__ldg(Wg + (mq + 0) * stride + coloff + c),
                       __ldg(Wg + (mq + 1) * stride + coloff + c),
                       __ldg(Wg + (mq + 2) * stride + coloff + c),
                       __ldg(Wg + (mq + 3) * stride + coloff + c));
}
__device__ __forceinline__ void stsWt(float* Wt, int tid, float4 w) {
    int c = tid >> 3, mq = (tid & 7) * 4;
    *(float4*)(Wt + c * 36 + mq) = w;
}

// Out[r][c] = sum_m In[r][m] * W[m][c] (+bias)(leaky), W staged as Wt[c][m].
// thread tile: rows tr..tr+3 (tr=(tid>>3)*4), cols c = (tid&7) + 8*cc, cc=0..3
__device__ __forceinline__ void gemm_tile(const float* __restrict__ In,
                                          const float* __restrict__ Wt,
                                          const float* __restrict__ bias,
                                          float* __restrict__ Out, int ostride,
                                          int coloff, int tid, int act) {
    const int tr = (tid >> 3) * 4;
    const int t7 = tid & 7;
    u64 acc[4][4];
    #pragma unroll
    for (int i = 0; i < 4; ++i)
        #pragma unroll
        for (int cc = 0; cc < 4; ++cc) acc[i][cc] = 0ull;

    #pragma unroll
    for (int m2 = 0; m2 < 32; m2 += 2) {
        u64 x[4], w[4];
        #pragma unroll
        for (int i = 0; i < 4; ++i)
            x[i] = *(const u64*)(In + (tr + i) * 36 + m2);
        #pragma unroll
        for (int cc = 0; cc < 4; ++cc)
            w[cc] = *(const u64*)(Wt + (t7 + 8 * cc) * 36 + m2);
        #pragma unroll
        for (int i = 0; i < 4; ++i)
            #pragma unroll
            for (int cc = 0; cc < 4; ++cc)
                ffma2(acc[i][cc], x[i], w[cc]);
    }
    #pragma unroll
    for (int cc = 0; cc < 4; ++cc) {
        int c = t7 + 8 * cc;
        float bv = bias ? __ldg(bias + c) : 0.f;
        #pragma unroll
        for (int i = 0; i < 4; ++i) {
            float2 p = unpk(acc[i][cc]);
            float s = p.x + p.y + bv;
            if (act) s = (s > 0.f) ? s : 0.2f * s;
            Out[(tr + i) * ostride + coloff + c] = s;
        }
    }
}

__global__ __launch_bounds__(256, 2) void batch_kernel(
    const float* __restrict__ z_table, const float* __restrict__ conv_W, const float* __restrict__ conv_b,
    const float* __restrict__ k1_W, const float* __restrict__ k1_b,
    const float* __restrict__ q1_W, const float* __restrict__ q1_b,
    const float* __restrict__ k2_W, const float* __restrict__ k2_b,
    const float* __restrict__ q2_W, const float* __restrict__ q2_b,
    const int* __restrict__ z, const int* __restrict__ edge_row,
    const int* __restrict__ node_i, const int* __restrict__ node_j)
{
    extern __shared__ float sm[];
    float* Wt   = sm;            // 1152 (32 x 36)
    float* X    = sm + 1152;     // stride 36
    float* XW   = sm + 5760;     // stride 36
    float* Q2   = sm + 10368;    // stride 68
    float* K2   = sm + 19072;    // stride 68
    float* dinv = sm + 27776;
    float* wcs  = sm + 27904;
    unsigned char* rows8 = (unsigned char*)(sm + 27908);  // 1024 bytes

    const int tid   = threadIdx.x;
    const int b     = blockIdx.x;
    const int gbase = b * 128;
    const int ebase = b * 1024;
    const int li    = node_i[b] - gbase;
    const int lj    = node_j[b] - gbase;

    // P0: setup + prefetch conv_W0 (transposed gather) + commit
    float4 wreg = ldgWt(conv_W, 32, 0, tid);
    if (tid < 128) {
        float dg = 9.f + (tid == li ? 1.f : 0.f) + (tid == lj ? 1.f : 0.f);
        dinv[tid] = rsqrtf(dg);
    }
    for (int e = tid; e < 1024; e += 256)
        rows8[(e & 127) * 8 + (e >> 7)] = (unsigned char)(edge_row[ebase + e] - gbase);
    for (int i = tid; i < 4096; i += 256) {
        int r = i >> 5, f = i & 31;
        X[r * 36 + f] = __ldg(z_table + __ldg(z + gbase + r) * 32 + f);
    }
    stsWt(Wt, tid, wreg);
    __syncthreads();

    const int warp = tid >> 5, lane = tid & 31;

    // 3 GCN layers; next-phase W prefetched during gemm/agg
    for (int l = 0; l < 3; ++l) {
        wreg = (l < 2) ? ldgWt(conv_W + (l + 1) * 1024, 32, 0, tid)
                       : ldgWt(k1_W, 32, 0, tid);
        gemm_tile(X, Wt, nullptr, XW, 36, 0, tid, 0);
        __syncthreads();
        for (int it = 0; it < 16; ++it) {
            int c = it * 8 + warp;
            float dc = dinv[c];
            float acc = __ldg(conv_b + l * 32 + lane) + dc * dc * XW[c * 36 + lane];
            #pragma unroll
            for (int k = 0; k < 8; ++k) {
                int r = rows8[c * 8 + k];
                acc = fmaf(dinv[r] * dc, XW[r * 36 + lane], acc);
            }
            if (c == li)      acc = fmaf(dinv[lj] * dc, XW[lj * 36 + lane], acc);
            else if (c == lj) acc = fmaf(dinv[li] * dc, XW[li * 36 + lane], acc);
            X[c * 36 + lane] = (l < 2) ? fmaxf(acc, 0.f) : acc;
        }
        stsWt(Wt, tid, wreg);
        __syncthreads();
    }

    // Attention projections (prefetch-next between phases)
    // k1 -> XW (leaky)
    wreg = ldgWt(k2_W, 64, 0, tid);
    gemm_tile(X, Wt, k1_b, XW, 36, 0, tid, 1);
    __syncthreads();
    stsWt(Wt, tid, wreg);  __syncthreads();
    // k2a -> Q2[:, 0:32]
    wreg = ldgWt(k2_W, 64, 32, tid);
    gemm_tile(XW, Wt, k2_b, Q2, 68, 0, tid, 0);
    __syncthreads();
    stsWt(Wt, tid, wreg);  __syncthreads();
    // k2b -> Q2[:, 32:64]
    wreg = ldgWt(q1_W, 32, 0, tid);
    gemm_tile(XW, Wt, k2_b + 32, Q2, 68, 32, tid, 0);
    __syncthreads();
    stsWt(Wt, tid, wreg);  __syncthreads();
    // q1 -> XW (leaky)
    wreg = ldgWt(q2_W, 64, 0, tid);
    gemm_tile(X, Wt, q1_b, XW, 36, 0, tid, 1);
    __syncthreads();
    stsWt(Wt, tid, wreg);  __syncthreads();
    // q2a -> K2[:, 0:32]
    wreg = ldgWt(q2_W, 64, 32, tid);
    gemm_tile(XW, Wt, q2_b, K2, 68, 0, tid, 0);
    __syncthreads();
    stsWt(Wt, tid, wreg);  __syncthreads();
    // q2b -> K2[:, 32:64]
    gemm_tile(XW, Wt, q2_b + 32, K2, 68, 32, tid, 0);
    __syncthreads();

    // Attention per (col c, head h): float4 dots, segment softmax -> compact rep
    const int c = tid & 127;
    const int h = tid >> 7;
    const float isq = 0.17677669529663687f;

    float4 kv4[8];
    {
        const float4* kr = (const float4*)(K2 + c * 68 + h * 32);
        #pragma unroll
        for (int u = 0; u < 8; ++u) kv4[u] = kr[u];
    }

    float w[8];
    int rws[8];
    #pragma unroll
    for (int k = 0; k < 8; ++k) {
        int r = rows8[c * 8 + k];
        rws[k] = r;
        const float4* qr = (const float4*)(Q2 + r * 68 + h * 32);
        float s = 0.f;
        #pragma unroll
        for (int u = 0; u < 8; ++u) {
            float4 q = qr[u];
            s = fmaf(q.x, kv4[u].x, s); s = fmaf(q.y, kv4[u].y, s);
            s = fmaf(q.z, kv4[u].z, s); s = fmaf(q.w, kv4[u].w, s);
        }
        w[k] = s * isq;
    }
    bool cand = (c == li) || (c == lj);
    float w8 = 0.f;
    if (cand) {
        int r = (c == li) ? lj : li;
        const float4* qr = (const float4*)(Q2 + r * 68 + h * 32);
        float s = 0.f;
        #pragma unroll
        for (int u = 0; u < 8; ++u) {
            float4 q = qr[u];
            s = fmaf(q.x, kv4[u].x, s); s = fmaf(q.y, kv4[u].y, s);
            s = fmaf(q.z, kv4[u].z, s); s = fmaf(q.w, kv4[u].w, s);
        }
        w8 = s * isq;
        wcs[h * 2 + (c == li ? 1 : 0)] = 1.f / (1.f + expf(-w8));
    }
    float wmax = w[0];
    #pragma unroll
    for (int k = 1; k < 8; ++k) wmax = fmaxf(wmax, w[k]);
    if (cand) wmax = fmaxf(wmax, w8);

    float ews[8];
    float sum8 = 0.f;
    #pragma unroll
    for (int k = 0; k < 8; ++k) { ews[k] = expf(w[k] - wmax); sum8 += ews[k]; }
    float ec = cand ? expf(w8 - wmax) : 0.f;
    float invp = 1.f / (sum8 + ec + 1e-16f);
    float invm = 1.f / (sum8 + 1e-16f);

    size_t vb = (((size_t)h * 256 + b) * 128 + c) * 12;
    *(float4*)(g_vals + vb)     = make_float4(ews[0], ews[1], ews[2], ews[3]);
    *(float4*)(g_vals + vb + 4) = make_float4(ews[4], ews[5], ews[6], ews[7]);
    *(float4*)(g_vals + vb + 8) = make_float4(ec, invp, invm, 0.f);
    if (h == 0) {
        uint2 pk;
        pk.x = (unsigned)rws[0] | ((unsigned)rws[1] << 8) | ((unsigned)rws[2] << 16) | ((unsigned)rws[3] << 24);
        pk.y = (unsigned)rws[4] | ((unsigned)rws[5] << 8) | ((unsigned)rws[6] << 16) | ((unsigned)rws[7] << 24);
        g_rows[b * 128 + c] = pk;
    }
    __syncthreads();
    if (tid < 2) g_omega[b * 2 + tid] = wcs[tid * 2] + wcs[tid * 2 + 1];
}

// ============================================================================
// Kernel 2: per-(h,b) m-chain (512 CTAs). Unchanged from R12.
// ============================================================================
#define CT 1024
#define SMC_FLOATS 36128

__device__ __forceinline__ float wred(float v) {
    #pragma unroll
    for (int off = 16; off; off >>= 1) v += __shfl_down_sync(0xffffffffu, v, off);
    return v;
}

__device__ __forceinline__ void spstep(const float* __restrict__ In, float* __restrict__ Out,
                                       const float* __restrict__ sv, const int* __restrict__ sr,
                                       int warp, int lane) {
    const float4* In4 = (const float4*)In;
    #pragma unroll
    for (int it = 0; it < 4; ++it) {
        int c = it * 32 + warp;
        float v[8]; int r[8];
        #pragma unroll
        for (int k = 0; k < 8; ++k) { v[k] = sv[c * 10 + k]; r[k] = sr[c * 10 + k]; }
        float4 acc = make_float4(0.f, 0.f, 0.f, 0.f);
        #pragma unroll
        for (int k = 0; k < 8; ++k) {
            float4 x = In4[r[k] * 32 + lane];
            acc.x = fmaf(v[k], x.x, acc.x);
            acc.y = fmaf(v[k], x.y, acc.y);
            acc.z = fmaf(v[k], x.z, acc.z);
            acc.w = fmaf(v[k], x.w, acc.w);
        }
        *(float4*)(Out + c * 128 + lane * 4) = acc;
    }
}

__global__ __launch_bounds__(CT) void chain_kernel(const int* __restrict__ node_i,
                                                   const int* __restrict__ node_j) {
    extern __shared__ float sm[];
    float* A    = sm;            // T2, later T4
    float* Bm   = sm + 16384;    // T_dense, then T3
    float* sv   = sm + 32768;    // [128][10] (8 used)
    int*   sr   = (int*)(sm + 34048);
    float* colb = sm + 35328;    // 4 x 128
    float* part = sm + 35840;    // [7][32]
    float* res  = sm + 36064;    // 16 (t2..t8)
    float* ent  = sm + 36080;    // [9][4] {ii,ij,ji,jj}

    const int tid  = threadIdx.x;
    const int bid  = blockIdx.x;
    const int h    = bid >> 8;
    const int b    = bid & 255;
    const int li   = node_i[b] - b * 128;
    const int lj   = node_j[b] - b * 128;
    const int warp = tid >> 5, lane = tid & 31;

    if (tid < 128) {
        int c = tid;
        uint2 pr = g_rows[b * 128 + c];
        const float4* gv = (const float4*)(g_vals + (((size_t)h * 256 + b) * 128 + c) * 12);
        float4 v0 = gv[0], v1 = gv[1], v2 = gv[2];
        float inv = v2.z;   // invm
        float ev[8] = {v0.x, v0.y, v0.z, v0.w, v1.x, v1.y, v1.z, v1.w};
        #pragma unroll
        for (int k = 0; k < 4; ++k) {
            sr[c * 10 + k]     = (pr.x >> (8 * k)) & 255;
            sr[c * 10 + 4 + k] = (pr.y >> (8 * k)) & 255;
        }
        #pragma unroll
        for (int k = 0; k < 8; ++k) sv[c * 10 + k] = ev[k] * inv;
    }
    for (int i = tid; i < 4096; i += CT)
        *(float4*)(Bm + i * 4) = make_float4(0.f, 0.f, 0.f, 0.f);
    __syncthreads();                                              // (1)

    // densify T into Bm: one atomic per (row, slot)
    {
        int c = tid >> 3, k = tid & 7;
        atomicAdd(&Bm[c * 128 + sr[c * 10 + k]], sv[c * 10 + k]);
    }
    __syncthreads();                                              // (2)

    spstep(Bm, A, sv, sr, warp, lane);   // A = T * T_dense = T2
    __syncthreads();                                              // (3)

    // phase A: t2 partials, ent[0..2]; then T3 = T*T2 (overwrites T_dense)
    {
        float p = (lane < 4) ? A[(4 * warp + lane) * 129] : 0.f;
        p = wred(p);
        if (lane == 0) part[warp] = p;
        if (warp == 31 && lane == 0) {
            ent[8]  = A[li * 129];        ent[9]  = A[li * 128 + lj];
            ent[10] = A[lj * 128 + li];   ent[11] = A[lj * 129];
        }
        if (warp == 28 && lane == 0) { ent[0] = 1.f; ent[1] = 0.f; ent[2] = 0.f; ent[3] = 1.f; }
        if (warp == 29 && lane < 2) {
            int u = lane ? lj : li;
            float eu = 0.f, ev_ = 0.f;
            #pragma unroll
            for (int k = 0; k < 8; ++k) {
                int r = sr[u * 10 + k];
                float v = sv[u * 10 + k];
                if (r == li) eu += v;
                if (r == lj) ev_ += v;
            }
            ent[4 + 2 * lane] = eu;
            ent[5 + 2 * lane] = ev_;
        }
    }
    spstep(A, Bm, sv, sr, warp, lane);
    __syncthreads();                                              // (4)

    // phase B: t3 partials + ent[3]; then T4 = T*T3 (overwrites T2)
    {
        float p = (lane < 4) ? Bm[(4 * warp + lane) * 129] : 0.f;
        p = wred(p);
        if (lane == 0) part[32 + warp] = p;
        if (warp == 31 && lane == 0) {
            ent[12] = Bm[li * 129];       ent[13] = Bm[li * 128 + lj];
            ent[14] = Bm[lj * 128 + li];  ent[15] = Bm[lj * 129];
        }
    }
    spstep(Bm, A, sv, sr, warp, lane);
    __syncthreads();                                              // (5)

    // phase C: t4/t5 partials, walk, ent[4..5], columns
    {
        float p4 = (lane < 4) ? A[(4 * warp + lane) * 129] : 0.f;
        float p5 = 0.f;
        if (lane < 4) {
            int rw = 4 * warp + lane;
            #pragma unroll
            for (int k = 0; k < 8; ++k)
                p5 = fmaf(sv[rw * 10 + k], A[sr[rw * 10 + k] * 128 + rw], p5);
        }
        float t6 = 0.f, t7 = 0.f, t8 = 0.f;
        for (int g = tid; g < 8064; g += CT) {
            int d = (g >> 7) + 1;
            int a = g & 127;
            int y = (a + d) & 127;
            float x3ab = Bm[a * 128 + y], x3ba = Bm[y * 128 + a];
            float x4ab = A[a * 128 + y],  x4ba = A[y * 128 + a];
            t6 = fmaf(2.f * x3ab, x3ba, t6);
            t7 = fmaf(x3ab, x4ba, fmaf(x3ba, x4ab, t7));
            t8 = fmaf(2.f * x4ab, x4ba, t8);
        }
        if (tid < 64) {
            int a = tid, y = a + 64;
            float x3ab = Bm[a * 128 + y], x3ba = Bm[y * 128 + a];
            float x4ab = A[a * 128 + y],  x4ba = A[y * 128 + a];
            t6 = fmaf(2.f * x3ab, x3ba, t6);
            t7 = fmaf(x3ab, x4ba, fmaf(x3ba, x4ab, t7));
            t8 = fmaf(2.f * x4ab, x4ba, t8);
        }
        if (tid < 128) {
            float d3 = Bm[tid * 129], d4 = A[tid * 129];
            t6 = fmaf(d3, d3, t6);
            t7 = fmaf(d3, d4, t7);
            t8 = fmaf(d4, d4, t8);
        }
        p4 = wred(p4); p5 = wred(p5);
        t6 = wred(t6); t7 = wred(t7); t8 = wred(t8);
        if (lane == 0) {
            part[2 * 32 + warp] = p4;
            part[3 * 32 + warp] = p5;
            part[4 * 32 + warp] = t6;
            part[5 * 32 + warp] = t7;
            part[6 * 32 + warp] = t8;
        }
        if (warp == 31 && lane == 0) {
            ent[16] = A[li * 129];        ent[17] = A[li * 128 + lj];
            ent[18] = A[lj * 128 + li];   ent[19] = A[lj * 129];
        }
        if (warp == 30 && lane < 4) {
            int u = (lane < 2) ? li : lj;
            int v = (lane & 1) ? lj : li;
            float s = 0.f;
            #pragma unroll
            for (int k = 0; k < 8; ++k)
                s = fmaf(sv[u * 10 + k], A[sr[u * 10 + k] * 128 + v], s);
            ent[20 + lane] = s;
        }
        if (tid >= 512) {
            int t = tid - 512;
            int w = t >> 7, m = t & 127;
            const float* M = (w < 2) ? Bm : A;
            int v = (w & 1) ? lj : li;
            colb[w * 128 + m] = M[m * 128 + v];
        }
    }
    __syncthreads();                                              // (6)

    // phase D: 12 dots -> ent[6..8]; final trace reductions -> res[0..6]
    if (warp < 12) {
        const float* R; int u; const float* C;
        if (warp < 4)      { R = Bm; u = (warp < 2) ? li : lj; C = colb + (warp & 1) * 128; }
        else if (warp < 8) { R = Bm; u = (warp < 6) ? li : lj; C = colb + (2 + (warp & 1)) * 128; }
        else               { R = A;  u = (warp < 10) ? li : lj; C = colb + (2 + (warp & 1)) * 128; }
        float s = 0.f;
        #pragma unroll
        for (int q = 0; q < 4; ++q) { int m = lane + 32 * q; s = fmaf(R[u * 128 + m], C[m], s); }
        s = wred(s);
        if (lane == 0) ent[(6 + (warp >> 2)) * 4 + (warp & 3)] = s;
    }
    if (warp >= 16 && warp < 23) {
        float s = part[(warp - 16) * 32 + lane];
        s = wred(s);
        if (lane == 0) res[warp - 16] = s;
    }
    __syncthreads();                                              // (7)

    const size_t mc = (size_t)(2 + h) * 256 + b;
    if (tid < 7)       g_feats[mc * 21 + tid] = res[tid];
    else if (tid < 14) { int k = tid - 7 + 2;  g_feats[mc * 21 + tid] = ent[k * 4] + ent[k * 4 + 3]; }
    else if (tid < 21) { int k = tid - 14 + 2; g_feats[mc * 21 + tid] = ent[k * 4 + 1] + ent[k * 4 + 2]; }
    else if (tid < 57) g_ent[((size_t)h * 256 + b) * 36 + tid - 21] = ent[tid - 21];
}

// ============================================================================
// Kernel 3: warp-per-batch MLP (32 blocks x 256 threads); register DP.
// ============================================================================
__global__ __launch_bounds__(256) void mlp_kernel(
    const float* __restrict__ W1, const float* __restrict__ b1,
    const float* __restrict__ W2, const float* __restrict__ b2,
    const int* __restrict__ node_i, const int* __restrict__ node_j,
    float* __restrict__ out) {
    const int wp = threadIdx.x >> 5;
    const int t  = threadIdx.x & 31;
    const int b  = blockIdx.x * 8 + wp;
    __shared__ float feat[8][72];
    __shared__ float mf[8][2][21];
    __shared__ float entS[8][2][36];
    __shared__ float pf[8][2][21];

    for (int q = t; q < 42; q += 32) mf[wp][q / 21][q % 21] = g_feats[((size_t)(2 + q / 21) * 256 + b) * 21 + q % 21];
    for (int q = t; q < 72; q += 32) entS[wp][q / 36][q % 36] = g_ent[((size_t)(q / 36) * 256 + b) * 36 + q % 36];
    __syncwarp();

    if (t == 0 || t == 16) {
        const int h = t >> 4;
        float E[36], G[32], Wp[32], Wn[32], Xc[36], tc[9];
        #pragma unroll
        for (int q = 0; q < 36; ++q) E[q] = entS[wp][h][q];
        const int li = node_i[b] - b * 128;
        const int lj = node_j[b] - b * 128;
        const float* gvi = g_vals + (((size_t)h * 256 + b) * 128 + li) * 12 + 8;
        const float* gvj = g_vals + (((size_t)h * 256 + b) * 128 + lj) * 12 + 8;
        float ai = gvi[1] / gvi[2], bi = gvi[0] * gvi[1];
        float aj = gvj[1] / gvj[2], bj = gvj[0] * gvj[1];

        #pragma unroll
        for (int a = 0; a < 8; ++a) {
            G[a * 4 + 0] = (ai - 1.f) * E[(a + 1) * 4 + 0] + bi * E[a * 4 + 2];
            G[a * 4 + 1] = (ai - 1.f) * E[(a + 1) * 4 + 1] + bi * E[a * 4 + 3];
            G[a * 4 + 2] = (aj - 1.f) * E[(a + 1) * 4 + 2] + bj * E[a * 4 + 0];
            G[a * 4 + 3] = (aj - 1.f) * E[(a + 1) * 4 + 3] + bj * E[a * 4 + 1];
        }
        #pragma unroll
        for (int k = 0; k < 9; ++k) {
            tc[k] = 0.f;
            Xc[k * 4] = 0.f; Xc[k * 4 + 1] = 0.f; Xc[k * 4 + 2] = 0.f; Xc[k * 4 + 3] = 0.f;
        }
        #pragma unroll
        for (int a = 0; a < 8; ++a) {
            Wp[a * 4 + 0] = G[a * 4 + 0]; Wp[a * 4 + 1] = G[a * 4 + 1];
            Wp[a * 4 + 2] = G[a * 4 + 2]; Wp[a * 4 + 3] = G[a * 4 + 3];
            tc[a + 1] += G[a * 4 + 0] + G[a * 4 + 3];
        }
        #pragma unroll
        for (int bb = 0; bb < 8; ++bb) {
            float t0 = E[bb * 4 + 0] * G[0] + E[bb * 4 + 1] * G[2];
            float t1 = E[bb * 4 + 0] * G[1] + E[bb * 4 + 1] * G[3];
            float t2 = E[bb * 4 + 2] * G[0] + E[bb * 4 + 3] * G[2];
            float t3 = E[bb * 4 + 2] * G[1] + E[bb * 4 + 3] * G[3];
            Xc[(bb + 1) * 4 + 0] += t0; Xc[(bb + 1) * 4 + 1] += t1;
            Xc[(bb + 1) * 4 + 2] += t2; Xc[(bb + 1) * 4 + 3] += t3;
        }
        #pragma unroll
        for (int c = 1; c < 8; ++c) {
            #pragma unroll
            for (int a = 0; a < 8; ++a) {
                if (a <= 7 - c) {
                    float t0 = Wp[0] * G[a * 4 + 0] + Wp[1] * G[a * 4 + 2];
                    float t1 = Wp[0] * G[a * 4 + 1] + Wp[1] * G[a * 4 + 3];
                    float t2 = Wp[2] * G[a * 4 + 0] + Wp[3] * G[a * 4 + 2];
                    float t3 = Wp[2] * G[a * 4 + 1] + Wp[3] * G[a * 4 + 3];
                    Wn[a * 4 + 0] = Wp[(a + 1) * 4 + 0] + t0;
                    Wn[a * 4 + 1] = Wp[(a + 1) * 4 + 1] + t1;
                    Wn[a * 4 + 2] = Wp[(a + 1) * 4 + 2] + t2;
                    Wn[a * 4 + 3] = Wp[(a + 1) * 4 + 3] + t3;
                    tc[a + c + 1] += Wn[a * 4 + 0] + Wn[a * 4 + 3];
                }
            }
            #pragma unroll
            for (int bb = 0; bb < 8; ++bb) {
                if (bb <= 7 - c) {
                    float t0 = E[bb * 4 + 0] * Wn[0] + E[bb * 4 + 1] * Wn[2];
                    float t1 = E[bb * 4 + 0] * Wn[1] + E[bb * 4 + 1] * Wn[3];
                    float t2 = E[bb * 4 + 2] * Wn[0] + E[bb * 4 + 3] * Wn[2];
                    float t3 = E[bb * 4 + 2] * Wn[1] + E[bb * 4 + 3] * Wn[3];
                    Xc[(bb + c + 1) * 4 + 0] += t0; Xc[(bb + c + 1) * 4 + 1] += t1;
                    Xc[(bb + c + 1) * 4 + 2] += t2; Xc[(bb + c + 1) * 4 + 3] += t3;
                }
            }
            #pragma unroll
            for (int a = 0; a < 8; ++a) {
                if (a <= 7 - c) {
                    Wp[a * 4 + 0] = Wn[a * 4 + 0]; Wp[a * 4 + 1] = Wn[a * 4 + 1];
                    Wp[a * 4 + 2] = Wn[a * 4 + 2]; Wp[a * 4 + 3] = Wn[a * 4 + 3];
                }
            }
        }
        #pragma unroll
        for (int k = 2; k <= 8; ++k) {
            pf[wp][h][k - 2]      = mf[wp][h][k - 2] + tc[k];
            pf[wp][h][7 + k - 2]  = E[k * 4 + 0] + E[k * 4 + 3] + Xc[k * 4 + 0] + Xc[k * 4 + 3];
            pf[wp][h][14 + k - 2] = E[k * 4 + 1] + E[k * 4 + 2] + Xc[k * 4 + 1] + Xc[k * 4 + 2];
        }
    }
    __syncwarp();

    for (int s = t; s < 72; s += 32) {
        float v;
        if (s < 14) {
            int h = s / 7, k = s % 7;
            v = pf[wp][h][k] - mf[wp][h][k];
        } else if (s < 16) {
            v = g_omega[b * 2 + (s - 14)];
        } else {
            int m = (s - 16) % 14;
            int blk = (s - 16) / 14;
            int h = m / 7, k = m % 7;
            if (blk == 0)      v = pf[wp][h][7 + k];
            else if (blk == 1) v = mf[wp][h][7 + k];
            else if (blk == 2) v = pf[wp][h][14 + k];
            else               v = mf[wp][h][14 + k];
        }
        feat[wp][s] = v;
    }
    __syncwarp();

    float h1 = b1[t];
    #pragma unroll 8
    for (int m = 0; m < 72; ++m) h1 = fmaf(feat[wp][m], W1[m * 32 + t], h1);
    h1 = fmaxf(h1, 0.f);
    float v = h1 * W2[t];
    #pragma unroll
    for (int off = 16; off; off >>= 1) v += __shfl_down_sync(0xffffffffu, v, off);
    if (t == 0) out[b] = v + b2[0];
}

// ============================================================================
extern "C" void kernel_launch(void* const* d_in, const int* in_sizes, int n_in,
                              void* d_out, int out_size) {
    (void)in_sizes; (void)n_in; (void)out_size;
    const float* z_table = (const float*)d_in[0];
    const float* conv_W  = (const float*)d_in[1];
    const float* conv_b  = (const float*)d_in[2];
    const float* k1_W    = (const float*)d_in[3];
    const float* k1_b    = (const float*)d_in[4];
    const float* q1_W    = (const float*)d_in[5];
    const float* q1_b    = (const float*)d_in[6];
    const float* k2_W    = (const float*)d_in[7];
    const float* k2_b    = (const float*)d_in[8];
    const float* q2_W    = (const float*)d_in[9];
    const float* q2_b    = (const float*)d_in[10];
    const float* mlp_W1  = (const float*)d_in[11];
    const float* mlp_b1  = (const float*)d_in[12];
    const float* mlp_W2  = (const float*)d_in[13];
    const float* mlp_b2  = (const float*)d_in[14];
    const int*   z        = (const int*)d_in[15];
    const int*   edge_row = (const int*)d_in[16];
    const int*   node_i   = (const int*)d_in[20];
    const int*   node_j   = (const int*)d_in[21];
    float* out = (float*)d_out;

    cudaFuncSetAttribute(batch_kernel, cudaFuncAttributeMaxDynamicSharedMemorySize, SMB_FLOATS * 4);
    cudaFuncSetAttribute(chain_kernel, cudaFuncAttributeMaxDynamicSharedMemorySize, SMC_FLOATS * 4);

    batch_kernel<<<NB, 256, SMB_FLOATS * 4>>>(
        z_table, conv_W, conv_b, k1_W, k1_b, q1_W, q1_b,
        k2_W, k2_b, q2_W, q2_b, z, edge_row, node_i, node_j);
    chain_kernel<<<2 * NB, CT, SMC_FLOATS * 4>>>(node_i, node_j);
    mlp_kernel<<<32, 256>>>(mlp_W1, mlp_b1, mlp_W2, mlp_b2, node_i, node_j, out);
}

// round 14
// speedup vs baseline: 1.0031x; 1.0031x over previous
#include <cuda_runtime.h>
#include <math.h>

#define NB 256
typedef unsigned long long u64;

// Compact global scratch (static; no runtime allocation)
__device__ float g_vals[(size_t)2 * 256 * 128 * 12];  // [h][b][c]{ews0..7, ec, invp, invm, pad}
__device__ uint2 g_rows[256 * 128];                   // [b][c] 8 packed row bytes
__device__ float g_feats[4 * NB * 21];                // m-chains at slots (2+h)*256+b
__device__ float g_ent[2 * 256 * 36];                 // [h][b]: T^a entries (a=0..8)x{ii,ij,ji,jj}
__device__ float g_omega[NB * 2];

// ---------------- packed fp32 helpers ----------------
__device__ __forceinline__ void ffma2(u64& a, u64 x, u64 y) {
    asm("fma.rn.f32x2 %0, %1, %2, %0;" : "+l"(a) : "l"(x), "l"(y));
}
__device__ __forceinline__ float2 unpk(u64 v) {
    float lo, hi; asm("mov.b64 {%0, %1}, %2;" : "=f"(lo), "=f"(hi) : "l"(v));
    return make_float2(lo, hi);
}

// ============================================================================
// Kernel 1: per-batch GCN + attention. Pack-free m-paired f32x2 GEMMs,
// conflict-free strides: X/XW stride 38, Wt stride 36.
// smem floats: Wt 0(1152) X 1152(4864) XW 6016(4864) Q2 10880(8704,str68)
//   K2 19584(8704) dinv 28288(128) wcs 28416(4) rows8 28420(256)
//   total 28676 floats = 112.0KB -> 2 CTA/SM
// ============================================================================
#define SMB_FLOATS 28676
#define XS 38

// gather-transpose prefetch: thread (c = tid>>3, mq = (tid&7)*4) fetches
// W[mq..mq+3][coloff + c] from row-major gmem W
__device__ __forceinline__ float4 ldgWt(const float* __restrict__ Wg, int stride,
                                        int coloff, int tid) {
    int c = tid >> 3, mq = (tid & 7) * 4;
    return make_float4(__ldg(Wg + (mq + 0) * stride + coloff + c),
                       __ldg(Wg + (mq + 1) * stride + coloff + c),
                       __ldg(Wg + (mq + 2) * stride + coloff + c),
                       __ldg(Wg + (mq + 3) * stride + coloff + c));
}
__device__ __forceinline__ void stsWt(float* Wt, int tid, float4 w) {
    int c = tid >> 3, mq = (tid & 7) * 4;
    *(float4*)(Wt + c * 36 + mq) = w;
}

// Out[r][c] = sum_m In[r][m] * W[m][c] (+bias)(leaky), W staged as Wt[c][m].
// thread tile: rows tr..tr+3, cols c = (tid&7) + 8*cc
__device__ __forceinline__ void gemm_tile(const float* __restrict__ In,
                                          const float* __restrict__ Wt,
                                          const float* __restrict__ bias,
                                          float* __restrict__ Out, int ostride,
                                          int coloff, int tid, int act) {
    const int tr = (tid >> 3) * 4;
    const int t7 = tid & 7;
    u64 acc[4][4];
    #pragma unroll
    for (int i = 0; i < 4; ++i)
        #pragma unroll
        for (int cc = 0; cc < 4; ++cc) acc[i][cc] = 0ull;

    #pragma unroll
    for (int m2 = 0; m2 < 32; m2 += 2) {
        u64 x[4], w[4];
        #pragma unroll
        for (int i = 0; i < 4; ++i)
            x[i] = *(const u64*)(In + (tr + i) * XS + m2);
        #pragma unroll
        for (int cc = 0; cc < 4; ++cc)
            w[cc] = *(const u64*)(Wt + (t7 + 8 * cc) * 36 + m2);
        #pragma unroll
        for (int i = 0; i < 4; ++i)
            #pragma unroll
            for (int cc = 0; cc < 4; ++cc)
                ffma2(acc[i][cc], x[i], w[cc]);
    }
    #pragma unroll
    for (int cc = 0; cc < 4; ++cc) {
        int c = t7 + 8 * cc;
        float bv = bias ? __ldg(bias + c) : 0.f;
        #pragma unroll
        for (int i = 0; i < 4; ++i) {
            float2 p = unpk(acc[i][cc]);
            float s = p.x + p.y + bv;
            if (act) s = (s > 0.f) ? s : 0.2f * s;
            Out[(tr + i) * ostride + coloff + c] = s;
        }
    }
}

__global__ __launch_bounds__(256, 2) void batch_kernel(
    const float* __restrict__ z_table, const float* __restrict__ conv_W, const float* __restrict__ conv_b,
    const float* __restrict__ k1_W, const float* __restrict__ k1_b,
    const float* __restrict__ q1_W, const float* __restrict__ q1_b,
    const float* __restrict__ k2_W, const float* __restrict__ k2_b,
    const float* __restrict__ q2_W, const float* __restrict__ q2_b,
    const int* __restrict__ z, const int* __restrict__ edge_row,
    const int* __restrict__ node_i, const int* __restrict__ node_j)
{
    extern __shared__ float sm[];
    float* Wt   = sm;            // 1152 (32 x 36)
    float* X    = sm + 1152;     // stride 38
    float* XW   = sm + 6016;     // stride 38
    float* Q2   = sm + 10880;    // stride 68
    float* K2   = sm + 19584;    // stride 68
    float* dinv = sm + 28288;
    float* wcs  = sm + 28416;
    unsigned char* rows8 = (unsigned char*)(sm + 28420);  // 1024 bytes

    const int tid   = threadIdx.x;
    const int b     = blockIdx.x;
    const int gbase = b * 128;
    const int ebase = b * 1024;
    const int li    = node_i[b] - gbase;
    const int lj    = node_j[b] - gbase;

    // P0: setup + prefetch conv_W0 (transposed gather) + commit
    float4 wreg = ldgWt(conv_W, 32, 0, tid);
    if (tid < 128) {
        float dg = 9.f + (tid == li ? 1.f : 0.f) + (tid == lj ? 1.f : 0.f);
        dinv[tid] = rsqrtf(dg);
    }
    for (int e = tid; e < 1024; e += 256)
        rows8[(e & 127) * 8 + (e >> 7)] = (unsigned char)(edge_row[ebase + e] - gbase);
    for (int i = tid; i < 4096; i += 256) {
        int r = i >> 5, f = i & 31;
        X[r * XS + f] = __ldg(z_table + __ldg(z + gbase + r) * 32 + f);
    }
    stsWt(Wt, tid, wreg);
    __syncthreads();

    const int warp = tid >> 5, lane = tid & 31;

    // 3 GCN layers; next-phase W prefetched during gemm/agg
    for (int l = 0; l < 3; ++l) {
        wreg = (l < 2) ? ldgWt(conv_W + (l + 1) * 1024, 32, 0, tid)
                       : ldgWt(k1_W, 32, 0, tid);
        gemm_tile(X, Wt, nullptr, XW, XS, 0, tid, 0);
        __syncthreads();
        for (int it = 0; it < 16; ++it) {
            int c = it * 8 + warp;
            float dc = dinv[c];
            float acc = __ldg(conv_b + l * 32 + lane) + dc * dc * XW[c * XS + lane];
            #pragma unroll
            for (int k = 0; k < 8; ++k) {
                int r = rows8[c * 8 + k];
                acc = fmaf(dinv[r] * dc, XW[r * XS + lane], acc);
            }
            if (c == li)      acc = fmaf(dinv[lj] * dc, XW[lj * XS + lane], acc);
            else if (c == lj) acc = fmaf(dinv[li] * dc, XW[li * XS + lane], acc);
            X[c * XS + lane] = (l < 2) ? fmaxf(acc, 0.f) : acc;
        }
        stsWt(Wt, tid, wreg);
        __syncthreads();
    }

    // Attention projections (prefetch-next between phases)
    // k1 -> XW (leaky)
    wreg = ldgWt(k2_W, 64, 0, tid);
    gemm_tile(X, Wt, k1_b, XW, XS, 0, tid, 1);
    __syncthreads();
    stsWt(Wt, tid, wreg);  __syncthreads();
    // k2a -> Q2[:, 0:32]
    wreg = ldgWt(k2_W, 64, 32, tid);
    gemm_tile(XW, Wt, k2_b, Q2, 68, 0, tid, 0);
    __syncthreads();
    stsWt(Wt, tid, wreg);  __syncthreads();
    // k2b -> Q2[:, 32:64]
    wreg = ldgWt(q1_W, 32, 0, tid);
    gemm_tile(XW, Wt, k2_b + 32, Q2, 68, 32, tid, 0);
    __syncthreads();
    stsWt(Wt, tid, wreg);  __syncthreads();
    // q1 -> XW (leaky)
    wreg = ldgWt(q2_W, 64, 0, tid);
    gemm_tile(X, Wt, q1_b, XW, XS, 0, tid, 1);
    __syncthreads();
    stsWt(Wt, tid, wreg);  __syncthreads();
    // q2a -> K2[:, 0:32]
    wreg = ldgWt(q2_W, 64, 32, tid);
    gemm_tile(XW, Wt, q2_b, K2, 68, 0, tid, 0);
    __syncthreads();
    stsWt(Wt, tid, wreg);  __syncthreads();
    // q2b -> K2[:, 32:64]
    gemm_tile(XW, Wt, q2_b + 32, K2, 68, 32, tid, 0);
    __syncthreads();

    // Attention per (col c, head h): float4 dots, segment softmax -> compact rep
    const int c = tid & 127;
    const int h = tid >> 7;
    const float isq = 0.17677669529663687f;

    float4 kv4[8];
    {
        const float4* kr = (const float4*)(K2 + c * 68 + h * 32);
        #pragma unroll
        for (int u = 0; u < 8; ++u) kv4[u] = kr[u];
    }

    float w[8];
    int rws[8];
    #pragma unroll
    for (int k = 0; k < 8; ++k) {
        int r = rows8[c * 8 + k];
        rws[k] = r;
        const float4* qr = (const float4*)(Q2 + r * 68 + h * 32);
        float s = 0.f;
        #pragma unroll
        for (int u = 0; u < 8; ++u) {
            float4 q = qr[u];
            s = fmaf(q.x, kv4[u].x, s); s = fmaf(q.y, kv4[u].y, s);
            s = fmaf(q.z, kv4[u].z, s); s = fmaf(q.w, kv4[u].w, s);
        }
        w[k] = s * isq;
    }
    bool cand = (c == li) || (c == lj);
    float w8 = 0.f;
    if (cand) {
        int r = (c == li) ? lj : li;
        const float4* qr = (const float4*)(Q2 + r * 68 + h * 32);
        float s = 0.f;
        #pragma unroll
        for (int u = 0; u < 8; ++u) {
            float4 q = qr[u];
            s = fmaf(q.x, kv4[u].x, s); s = fmaf(q.y, kv4[u].y, s);
            s = fmaf(q.z, kv4[u].z, s); s = fmaf(q.w, kv4[u].w, s);
        }
        w8 = s * isq;
        wcs[h * 2 + (c == li ? 1 : 0)] = 1.f / (1.f + expf(-w8));
    }
    float wmax = w[0];
    #pragma unroll
    for (int k = 1; k < 8; ++k) wmax = fmaxf(wmax, w[k]);
    if (cand) wmax = fmaxf(wmax, w8);

    float ews[8];
    float sum8 = 0.f;
    #pragma unroll
    for (int k = 0; k < 8; ++k) { ews[k] = expf(w[k] - wmax); sum8 += ews[k]; }
    float ec = cand ? expf(w8 - wmax) : 0.f;
    float invp = 1.f / (sum8 + ec + 1e-16f);
    float invm = 1.f / (sum8 + 1e-16f);

    size_t vb = (((size_t)h * 256 + b) * 128 + c) * 12;
    *(float4*)(g_vals + vb)     = make_float4(ews[0], ews[1], ews[2], ews[3]);
    *(float4*)(g_vals + vb + 4) = make_float4(ews[4], ews[5], ews[6], ews[7]);
    *(float4*)(g_vals + vb + 8) = make_float4(ec, invp, invm, 0.f);
    if (h == 0) {
        uint2 pk;
        pk.x = (unsigned)rws[0] | ((unsigned)rws[1] << 8) | ((unsigned)rws[2] << 16) | ((unsigned)rws[3] << 24);
        pk.y = (unsigned)rws[4] | ((unsigned)rws[5] << 8) | ((unsigned)rws[6] << 16) | ((unsigned)rws[7] << 24);
        g_rows[b * 128 + c] = pk;
    }
    __syncthreads();
    if (tid < 2) g_omega[b * 2 + tid] = wcs[tid * 2] + wcs[tid * 2 + 1];
}

// ============================================================================
// Kernel 2: per-(h,b) m-chain (512 CTAs). Unchanged (101.4us config).
// ============================================================================
#define CT 1024
#define SMC_FLOATS 36128

__device__ __forceinline__ float wred(float v) {
    #pragma unroll
    for (int off = 16; off; off >>= 1) v += __shfl_down_sync(0xffffffffu, v, off);
    return v;
}

__device__ __forceinline__ void spstep(const float* __restrict__ In, float* __restrict__ Out,
                                       const float* __restrict__ sv, const int* __restrict__ sr,
                                       int warp, int lane) {
    const float4* In4 = (const float4*)In;
    #pragma unroll
    for (int it = 0; it < 4; ++it) {
        int c = it * 32 + warp;
        float v[8]; int r[8];
        #pragma unroll
        for (int k = 0; k < 8; ++k) { v[k] = sv[c * 10 + k]; r[k] = sr[c * 10 + k]; }
        float4 acc = make_float4(0.f, 0.f, 0.f, 0.f);
        #pragma unroll
        for (int k = 0; k < 8; ++k) {
            float4 x = In4[r[k] * 32 + lane];
            acc.x = fmaf(v[k], x.x, acc.x);
            acc.y = fmaf(v[k], x.y, acc.y);
            acc.z = fmaf(v[k], x.z, acc.z);
            acc.w = fmaf(v[k], x.w, acc.w);
        }
        *(float4*)(Out + c * 128 + lane * 4) = acc;
    }
}

__global__ __launch_bounds__(CT) void chain_kernel(const int* __restrict__ node_i,
                                                   const int* __restrict__ node_j) {
    extern __shared__ float sm[];
    float* A    = sm;            // T2, later T4
    float* Bm   = sm + 16384;    // T_dense, then T3
    float* sv   = sm + 32768;    // [128][10] (8 used)
    int*   sr   = (int*)(sm + 34048);
    float* colb = sm + 35328;    // 4 x 128
    float* part = sm + 35840;    // [7][32]
    float* res  = sm + 36064;    // 16 (t2..t8)
    float* ent  = sm + 36080;    // [9][4] {ii,ij,ji,jj}

    const int tid  = threadIdx.x;
    const int bid  = blockIdx.x;
    const int h    = bid >> 8;
    const int b    = bid & 255;
    const int li   = node_i[b] - b * 128;
    const int lj   = node_j[b] - b * 128;
    const int warp = tid >> 5, lane = tid & 31;

    if (tid < 128) {
        int c = tid;
        uint2 pr = g_rows[b * 128 + c];
        const float4* gv = (const float4*)(g_vals + (((size_t)h * 256 + b) * 128 + c) * 12);
        float4 v0 = gv[0], v1 = gv[1], v2 = gv[2];
        float inv = v2.z;   // invm
        float ev[8] = {v0.x, v0.y, v0.z, v0.w, v1.x, v1.y, v1.z, v1.w};
        #pragma unroll
        for (int k = 0; k < 4; ++k) {
            sr[c * 10 + k]     = (pr.x >> (8 * k)) & 255;
            sr[c * 10 + 4 + k] = (pr.y >> (8 * k)) & 255;
        }
        #pragma unroll
        for (int k = 0; k < 8; ++k) sv[c * 10 + k] = ev[k] * inv;
    }
    for (int i = tid; i < 4096; i += CT)
        *(float4*)(Bm + i * 4) = make_float4(0.f, 0.f, 0.f, 0.f);
    __syncthreads();                                              // (1)

    // densify T into Bm: one atomic per (row, slot)
    {
        int c = tid >> 3, k = tid & 7;
        atomicAdd(&Bm[c * 128 + sr[c * 10 + k]], sv[c * 10 + k]);
    }
    __syncthreads();                                              // (2)

    spstep(Bm, A, sv, sr, warp, lane);   // A = T * T_dense = T2
    __syncthreads();                                              // (3)

    // phase A: t2 partials, ent[0..2]; then T3 = T*T2 (overwrites T_dense)
    {
        float p = (lane < 4) ? A[(4 * warp + lane) * 129] : 0.f;
        p = wred(p);
        if (lane == 0) part[warp] = p;
        if (warp == 31 && lane == 0) {
            ent[8]  = A[li * 129];        ent[9]  = A[li * 128 + lj];
            ent[10] = A[lj * 128 + li];   ent[11] = A[lj * 129];
        }
        if (warp == 28 && lane == 0) { ent[0] = 1.f; ent[1] = 0.f; ent[2] = 0.f; ent[3] = 1.f; }
        if (warp == 29 && lane < 2) {
            int u = lane ? lj : li;
            float eu = 0.f, ev_ = 0.f;
            #pragma unroll
            for (int k = 0; k < 8; ++k) {
                int r = sr[u * 10 + k];
                float v = sv[u * 10 + k];
                if (r == li) eu += v;
                if (r == lj) ev_ += v;
            }
            ent[4 + 2 * lane] = eu;
            ent[5 + 2 * lane] = ev_;
        }
    }
    spstep(A, Bm, sv, sr, warp, lane);
    __syncthreads();                                              // (4)

    // phase B: t3 partials + ent[3]; then T4 = T*T3 (overwrites T2)
    {
        float p = (lane < 4) ? Bm[(4 * warp + lane) * 129] : 0.f;
        p = wred(p);
        if (lane == 0) part[32 + warp] = p;
        if (warp == 31 && lane == 0) {
            ent[12] = Bm[li * 129];       ent[13] = Bm[li * 128 + lj];
            ent[14] = Bm[lj * 128 + li];  ent[15] = Bm[lj * 129];
        }
    }
    spstep(Bm, A, sv, sr, warp, lane);
    __syncthreads();                                              // (5)

    // phase C: t4/t5 partials, walk, ent[4..5], columns
    {
        float p4 = (lane < 4) ? A[(4 * warp + lane) * 129] : 0.f;
        float p5 = 0.f;
        if (lane < 4) {
            int rw = 4 * warp + lane;
            #pragma unroll
            for (int k = 0; k < 8; ++k)
                p5 = fmaf(sv[rw * 10 + k], A[sr[rw * 10 + k] * 128 + rw], p5);
        }
        float t6 = 0.f, t7 = 0.f, t8 = 0.f;
        for (int g = tid; g < 8064; g += CT) {
            int d = (g >> 7) + 1;
            int a = g & 127;
            int y = (a + d) & 127;
            float x3ab = Bm[a * 128 + y], x3ba = Bm[y * 128 + a];
            float x4ab = A[a * 128 + y],  x4ba = A[y * 128 + a];
            t6 = fmaf(2.f * x3ab, x3ba, t6);
            t7 = fmaf(x3ab, x4ba, fmaf(x3ba, x4ab, t7));
            t8 = fmaf(2.f * x4ab, x4ba, t8);
        }
        if (tid < 64) {
            int a = tid, y = a + 64;
            float x3ab = Bm[a * 128 + y], x3ba = Bm[y * 128 + a];
            float x4ab = A[a * 128 + y],  x4ba = A[y * 128 + a];
            t6 = fmaf(2.f * x3ab, x3ba, t6);
            t7 = fmaf(x3ab, x4ba, fmaf(x3ba, x4ab, t7));
            t8 = fmaf(2.f * x4ab, x4ba, t8);
        }
        if (tid < 128) {
            float d3 = Bm[tid * 129], d4 = A[tid * 129];
            t6 = fmaf(d3, d3, t6);
            t7 = fmaf(d3, d4, t7);
            t8 = fmaf(d4, d4, t8);
        }
        p4 = wred(p4); p5 = wred(p5);
        t6 = wred(t6); t7 = wred(t7); t8 = wred(t8);
        if (lane == 0) {
            part[2 * 32 + warp] = p4;
            part[3 * 32 + warp] = p5;
            part[4 * 32 + warp] = t6;
            part[5 * 32 + warp] = t7;
            part[6 * 32 + warp] = t8;
        }
        if (warp == 31 && lane == 0) {
            ent[16] = A[li * 129];        ent[17] = A[li * 128 + lj];
            ent[18] = A[lj * 128 + li];   ent[19] = A[lj * 129];
        }
        if (warp == 30 && lane < 4) {
            int u = (lane < 2) ? li : lj;
            int v = (lane & 1) ? lj : li;
            float s = 0.f;
            #pragma unroll
            for (int k = 0; k < 8; ++k)
                s = fmaf(sv[u * 10 + k], A[sr[u * 10 + k] * 128 + v], s);
            ent[20 + lane] = s;
        }
        if (tid >= 512) {
            int t = tid - 512;
            int w = t >> 7, m = t & 127;
            const float* M = (w < 2) ? Bm : A;
            int v = (w & 1) ? lj : li;
            colb[w * 128 + m] = M[m * 128 + v];
        }
    }
    __syncthreads();                                              // (6)

    // phase D: 12 dots -> ent[6..8]; final trace reductions -> res[0..6]
    if (warp < 12) {
        const float* R; int u; const float* C;
        if (warp < 4)      { R = Bm; u = (warp < 2) ? li : lj; C = colb + (warp & 1) * 128; }
        else if (warp < 8) { R = Bm; u = (warp < 6) ? li : lj; C = colb + (2 + (warp & 1)) * 128; }
        else               { R = A;  u = (warp < 10) ? li : lj; C = colb + (2 + (warp & 1)) * 128; }
        float s = 0.f;
        #pragma unroll
        for (int q = 0; q < 4; ++q) { int m = lane + 32 * q; s = fmaf(R[u * 128 + m], C[m], s); }
        s = wred(s);
        if (lane == 0) ent[(6 + (warp >> 2)) * 4 + (warp & 3)] = s;
    }
    if (warp >= 16 && warp < 23) {
        float s = part[(warp - 16) * 32 + lane];
        s = wred(s);
        if (lane == 0) res[warp - 16] = s;
    }
    __syncthreads();                                              // (7)

    const size_t mc = (size_t)(2 + h) * 256 + b;
    if (tid < 7)       g_feats[mc * 21 + tid] = res[tid];
    else if (tid < 14) { int k = tid - 7 + 2;  g_feats[mc * 21 + tid] = ent[k * 4] + ent[k * 4 + 3]; }
    else if (tid < 21) { int k = tid - 14 + 2; g_feats[mc * 21 + tid] = ent[k * 4 + 1] + ent[k * 4 + 2]; }
    else if (tid < 57) g_ent[((size_t)h * 256 + b) * 36 + tid - 21] = ent[tid - 21];
}

// ============================================================================
// Kernel 3: warp-per-batch MLP (32 blocks x 256 threads); register DP.
// ============================================================================
__global__ __launch_bounds__(256) void mlp_kernel(
    const float* __restrict__ W1, const float* __restrict__ b1,
    const float* __restrict__ W2, const float* __restrict__ b2,
    const int* __restrict__ node_i, const int* __restrict__ node_j,
    float* __restrict__ out) {
    const int wp = threadIdx.x >> 5;
    const int t  = threadIdx.x & 31;
    const int b  = blockIdx.x * 8 + wp;
    __shared__ float feat[8][72];
    __shared__ float mf[8][2][21];
    __shared__ float entS[8][2][36];
    __shared__ float pf[8][2][21];

    for (int q = t; q < 42; q += 32) mf[wp][q / 21][q % 21] = g_feats[((size_t)(2 + q / 21) * 256 + b) * 21 + q % 21];
    for (int q = t; q < 72; q += 32) entS[wp][q / 36][q % 36] = g_ent[((size_t)(q / 36) * 256 + b) * 36 + q % 36];
    __syncwarp();

    if (t == 0 || t == 16) {
        const int h = t >> 4;
        float E[36], G[32], Wp[32], Wn[32], Xc[36], tc[9];
        #pragma unroll
        for (int q = 0; q < 36; ++q) E[q] = entS[wp][h][q];
        const int li = node_i[b] - b * 128;
        const int lj = node_j[b] - b * 128;
        const float* gvi = g_vals + (((size_t)h * 256 + b) * 128 + li) * 12 + 8;
        const float* gvj = g_vals + (((size_t)h * 256 + b) * 128 + lj) * 12 + 8;
        float ai = gvi[1] / gvi[2], bi = gvi[0] * gvi[1];
        float aj = gvj[1] / gvj[2], bj = gvj[0] * gvj[1];

        #pragma unroll
        for (int a = 0; a < 8; ++a) {
            G[a * 4 + 0] = (ai - 1.f) * E[(a + 1) * 4 + 0] + bi * E[a * 4 + 2];
            G[a * 4 + 1] = (ai - 1.f) * E[(a + 1) * 4 + 1] + bi * E[a * 4 + 3];
            G[a * 4 + 2] = (aj - 1.f) * E[(a + 1) * 4 + 2] + bj * E[a * 4 + 0];
            G[a * 4 + 3] = (aj - 1.f) * E[(a + 1) * 4 + 3] + bj * E[a * 4 + 1];
        }
        #pragma unroll
        for (int k = 0; k < 9; ++k) {
            tc[k] = 0.f;
            Xc[k * 4] = 0.f; Xc[k * 4 + 1] = 0.f; Xc[k * 4 + 2] = 0.f; Xc[k * 4 + 3] = 0.f;
        }
        #pragma unroll
        for (int a = 0; a < 8; ++a) {
            Wp[a * 4 + 0] = G[a * 4 + 0]; Wp[a * 4 + 1] = G[a * 4 + 1];
            Wp[a * 4 + 2] = G[a * 4 + 2]; Wp[a * 4 + 3] = G[a * 4 + 3];
            tc[a + 1] += G[a * 4 + 0] + G[a * 4 + 3];
        }
        #pragma unroll
        for (int bb = 0; bb < 8; ++bb) {
            float t0 = E[bb * 4 + 0] * G[0] + E[bb * 4 + 1] * G[2];
            float t1 = E[bb * 4 + 0] * G[1] + E[bb * 4 + 1] * G[3];
            float t2 = E[bb * 4 + 2] * G[0] + E[bb * 4 + 3] * G[2];
            float t3 = E[bb * 4 + 2] * G[1] + E[bb * 4 + 3] * G[3];
            Xc[(bb + 1) * 4 + 0] += t0; Xc[(bb + 1) * 4 + 1] += t1;
            Xc[(bb + 1) * 4 + 2] += t2; Xc[(bb + 1) * 4 + 3] += t3;
        }
        #pragma unroll
        for (int c = 1; c < 8; ++c) {
            #pragma unroll
            for (int a = 0; a < 8; ++a) {
                if (a <= 7 - c) {
                    float t0 = Wp[0] * G[a * 4 + 0] + Wp[1] * G[a * 4 + 2];
                    float t1 = Wp[0] * G[a * 4 + 1] + Wp[1] * G[a * 4 + 3];
                    float t2 = Wp[2] * G[a * 4 + 0] + Wp[3] * G[a * 4 + 2];
                    float t3 = Wp[2] * G[a * 4 + 1] + Wp[3] * G[a * 4 + 3];
                    Wn[a * 4 + 0] = Wp[(a + 1) * 4 + 0] + t0;
                    Wn[a * 4 + 1] = Wp[(a + 1) * 4 + 1] + t1;
                    Wn[a * 4 + 2] = Wp[(a + 1) * 4 + 2] + t2;
                    Wn[a * 4 + 3] = Wp[(a + 1) * 4 + 3] + t3;
                    tc[a + c + 1] += Wn[a * 4 + 0] + Wn[a * 4 + 3];
                }
            }
            #pragma unroll
            for (int bb = 0; bb < 8; ++bb) {
                if (bb <= 7 - c) {
                    float t0 = E[bb * 4 + 0] * Wn[0] + E[bb * 4 + 1] * Wn[2];
                    float t1 = E[bb * 4 + 0] * Wn[1] + E[bb * 4 + 1] * Wn[3];
                    float t2 = E[bb * 4 + 2] * Wn[0] + E[bb * 4 + 3] * Wn[2];
                    float t3 = E[bb * 4 + 2] * Wn[1] + E[bb * 4 + 3] * Wn[3];
                    Xc[(bb + c + 1) * 4 + 0] += t0; Xc[(bb + c + 1) * 4 + 1] += t1;
                    Xc[(bb + c + 1) * 4 + 2] += t2; Xc[(bb + c + 1) * 4 + 3] += t3;
                }
            }
            #pragma unroll
            for (int a = 0; a < 8; ++a) {
                if (a <= 7 - c) {
                    Wp[a * 4 + 0] = Wn[a * 4 + 0]; Wp[a * 4 + 1] = Wn[a * 4 + 1];
                    Wp[a * 4 + 2] = Wn[a * 4 + 2]; Wp[a * 4 + 3] = Wn[a * 4 + 3];
                }
            }
        }
        #pragma unroll
        for (int k = 2; k <= 8; ++k) {
            pf[wp][h][k - 2]      = mf[wp][h][k - 2] + tc[k];
            pf[wp][h][7 + k - 2]  = E[k * 4 + 0] + E[k * 4 + 3] + Xc[k * 4 + 0] + Xc[k * 4 + 3];
            pf[wp][h][14 + k - 2] = E[k * 4 + 1] + E[k * 4 + 2] + Xc[k * 4 + 1] + Xc[k * 4 + 2];
        }
    }
    __syncwarp();

    for (int s = t; s < 72; s += 32) {
        float v;
        if (s < 14) {
            int h = s / 7, k = s % 7;
            v = pf[wp][h][k] - mf[wp][h][k];
        } else if (s < 16) {
            v = g_omega[b * 2 + (s - 14)];
        } else {
            int m = (s - 16) % 14;
            int blk = (s - 16) / 14;
            int h = m / 7, k = m % 7;
            if (blk == 0)      v = pf[wp][h][7 + k];
            else if (blk == 1) v = mf[wp][h][7 + k];
            else if (blk == 2) v = pf[wp][h][14 + k];
            else               v = mf[wp][h][14 + k];
        }
        feat[wp][s] = v;
    }
    __syncwarp();

    float h1 = b1[t];
    #pragma unroll 8
    for (int m = 0; m < 72; ++m) h1 = fmaf(feat[wp][m], W1[m * 32 + t], h1);
    h1 = fmaxf(h1, 0.f);
    float v = h1 * W2[t];
    #pragma unroll
    for (int off = 16; off; off >>= 1) v += __shfl_down_sync(0xffffffffu, v, off);
    if (t == 0) out[b] = v + b2[0];
}

// ============================================================================
extern "C" void kernel_launch(void* const* d_in, const int* in_sizes, int n_in,
                              void* d_out, int out_size) {
    (void)in_sizes; (void)n_in; (void)out_size;
    const float* z_table = (const float*)d_in[0];
    const float* conv_W  = (const float*)d_in[1];
    const float* conv_b  = (const float*)d_in[2];
    const float* k1_W    = (const float*)d_in[3];
    const float* k1_b    = (const float*)d_in[4];
    const float* q1_W    = (const float*)d_in[5];
    const float* q1_b    = (const float*)d_in[6];
    const float* k2_W    = (const float*)d_in[7];
    const float* k2_b    = (const float*)d_in[8];
    const float* q2_W    = (const float*)d_in[9];
    const float* q2_b    = (const float*)d_in[10];
    const float* mlp_W1  = (const float*)d_in[11];
    const float* mlp_b1  = (const float*)d_in[12];
    const float* mlp_W2  = (const float*)d_in[13];
    const float* mlp_b2  = (const float*)d_in[14];
    const int*   z        = (const int*)d_in[15];
    const int*   edge_row = (const int*)d_in[16];
    const int*   node_i   = (const int*)d_in[20];
    const int*   node_j   = (const int*)d_in[21];
    float* out = (float*)d_out;

    cudaFuncSetAttribute(batch_kernel, cudaFuncAttributeMaxDynamicSharedMemorySize, SMB_FLOATS * 4);
    cudaFuncSetAttribute(chain_kernel, cudaFuncAttributeMaxDynamicSharedMemorySize, SMC_FLOATS * 4);

    batch_kernel<<<NB, 256, SMB_FLOATS * 4>>>(
        z_table, conv_W, conv_b, k1_W, k1_b, q1_W, q1_b,
        k2_W, k2_b, q2_W, q2_b, z, edge_row, node_i, node_j);
    chain_kernel<<<2 * NB, CT, SMC_FLOATS * 4>>>(node_i, node_j);
    mlp_kernel<<<32, 256>>>(mlp_W1, mlp_b1, mlp_W2, mlp_b2, node_i, node_j, out);
}

// round 15
// speedup vs baseline: 1.0394x; 1.0362x over previous
#include <cuda_runtime.h>
#include <math.h>

#define NB 256
typedef unsigned long long u64;

// Compact global scratch (static; no runtime allocation)
__device__ float g_vals[(size_t)2 * 256 * 128 * 12];  // [h][b][c]{ews0..7, ec, invp, invm, pad}
__device__ uint2 g_rows[256 * 128];                   // [b][c] 8 packed row bytes
__device__ float g_feats[4 * NB * 21];                // m-chains at slots (2+h)*256+b
__device__ float g_ent[2 * 256 * 36];                 // [h][b]: T^a entries (a=0..8)x{ii,ij,ji,jj}
__device__ float g_omega[NB * 2];

// ---------------- packed fp32 helpers ----------------
__device__ __forceinline__ u64 pack2(float x) {
    u64 r; asm("mov.b64 %0, {%1, %1};" : "=l"(r) : "f"(x)); return r;
}
__device__ __forceinline__ void ffma2(u64& a, u64 x, u64 y) {
    asm("fma.rn.f32x2 %0, %1, %2, %0;" : "+l"(a) : "l"(x), "l"(y));
}
__device__ __forceinline__ float2 unpk(u64 v) {
    float lo, hi; asm("mov.b64 {%0, %1}, %2;" : "=f"(lo), "=f"(hi) : "l"(v));
    return make_float2(lo, hi);
}

// ============================================================================
// Kernel 1: per-batch GCN + attention. Column-paired f32x2 GEMMs +
// register-prefetched weights (the proven 45.4us configuration).
// smem floats: Wb 0(1024) X 1024(4608,str36) XW 5632(4608,str36)
//   Q2 10240(8704,str68) K2 18944(8704,str68) dinv 27648(128) wcs 27776(4)
//   rows8 27780(256 floats)  total 28036 floats = 112.1KB -> 2 CTA/SM
// ============================================================================
#define SMB_FLOATS 28036

__device__ __forceinline__ float4 ldgW(const float* __restrict__ Wg, int src_stride,
                                       int coloff, int tid) {
    int m = tid >> 3, c4 = (tid & 7) * 4;
    return __ldg((const float4*)(Wg + m * src_stride + coloff + c4));
}
__device__ __forceinline__ void stsW(float* Wb, int tid, float4 w) {
    int m = tid >> 3, c4 = (tid & 7) * 4;
    *(float4*)(Wb + m * 32 + c4) = w;
}

__device__ __forceinline__ void gemm_tile(const float* __restrict__ In,
                                          const float* __restrict__ Wb,
                                          const float* __restrict__ bias,
                                          float* __restrict__ Out, int ostride,
                                          int tid, int act) {
    const int tr = (tid >> 3) * 4;
    const int tc = (tid & 7) * 4;
    u64 acc[4][2];
    #pragma unroll
    for (int i = 0; i < 4; ++i) { acc[i][0] = 0ull; acc[i][1] = 0ull; }

    #pragma unroll
    for (int m4 = 0; m4 < 32; m4 += 4) {
        float4 a4[4];
        #pragma unroll
        for (int i = 0; i < 4; ++i)
            a4[i] = *(const float4*)(In + (tr + i) * 36 + m4);
        #pragma unroll
        for (int mm = 0; mm < 4; ++mm) {
            u64 w01 = *(const u64*)(Wb + (m4 + mm) * 32 + tc);
            u64 w23 = *(const u64*)(Wb + (m4 + mm) * 32 + tc + 2);
            #pragma unroll
            for (int i = 0; i < 4; ++i) {
                float am = (mm == 0) ? a4[i].x : (mm == 1) ? a4[i].y
                         : (mm == 2) ? a4[i].z : a4[i].w;
                u64 ap = pack2(am);
                ffma2(acc[i][0], ap, w01);
                ffma2(acc[i][1], ap, w23);
            }
        }
    }
    float4 bv = make_float4(0.f, 0.f, 0.f, 0.f);
    if (bias) bv = __ldg((const float4*)(bias + tc));
    #pragma unroll
    for (int i = 0; i < 4; ++i) {
        float2 p0 = unpk(acc[i][0]);
        float2 p1 = unpk(acc[i][1]);
        float4 o;
        o.x = p0.x + bv.x; o.y = p0.y + bv.y;
        o.z = p1.x + bv.z; o.w = p1.y + bv.w;
        if (act) {
            o.x = (o.x > 0.f) ? o.x : 0.2f * o.x;
            o.y = (o.y > 0.f) ? o.y : 0.2f * o.y;
            o.z = (o.z > 0.f) ? o.z : 0.2f * o.z;
            o.w = (o.w > 0.f) ? o.w : 0.2f * o.w;
        }
        *(float4*)(Out + (tr + i) * ostride + tc) = o;
    }
}

__global__ __launch_bounds__(256, 2) void batch_kernel(
    const float* __restrict__ z_table, const float* __restrict__ conv_W, const float* __restrict__ conv_b,
    const float* __restrict__ k1_W, const float* __restrict__ k1_b,
    const float* __restrict__ q1_W, const float* __restrict__ q1_b,
    const float* __restrict__ k2_W, const float* __restrict__ k2_b,
    const float* __restrict__ q2_W, const float* __restrict__ q2_b,
    const int* __restrict__ z, const int* __restrict__ edge_row,
    const int* __restrict__ node_i, const int* __restrict__ node_j)
{
    extern __shared__ float sm[];
    float* Wb   = sm;            // 1024
    float* X    = sm + 1024;     // stride 36
    float* XW   = sm + 5632;     // stride 36
    float* Q2   = sm + 10240;    // stride 68
    float* K2   = sm + 18944;    // stride 68
    float* dinv = sm + 27648;
    float* wcs  = sm + 27776;
    unsigned char* rows8 = (unsigned char*)(sm + 27780);  // 1024 bytes

    const int tid   = threadIdx.x;
    const int b     = blockIdx.x;
    const int gbase = b * 128;
    const int ebase = b * 1024;
    const int li    = node_i[b] - gbase;
    const int lj    = node_j[b] - gbase;

    // P0: setup + prefetch conv_W0 + commit
    float4 wreg = ldgW(conv_W, 32, 0, tid);
    if (tid < 128) {
        float dg = 9.f + (tid == li ? 1.f : 0.f) + (tid == lj ? 1.f : 0.f);
        dinv[tid] = rsqrtf(dg);
    }
    for (int e = tid; e < 1024; e += 256)
        rows8[(e & 127) * 8 + (e >> 7)] = (unsigned char)(edge_row[ebase + e] - gbase);
    for (int i = tid; i < 4096; i += 256) {
        int r = i >> 5, f = i & 31;
        X[r * 36 + f] = __ldg(z_table + __ldg(z + gbase + r) * 32 + f);
    }
    stsW(Wb, tid, wreg);
    __syncthreads();

    const int warp = tid >> 5, lane = tid & 31;

    // 3 GCN layers; next-phase W prefetched during gemm/agg
    for (int l = 0; l < 3; ++l) {
        wreg = (l < 2) ? ldgW(conv_W + (l + 1) * 1024, 32, 0, tid)
                       : ldgW(k1_W, 32, 0, tid);
        gemm_tile(X, Wb, nullptr, XW, 36, tid, 0);
        __syncthreads();
        const float bias_l = __ldg(conv_b + l * 32 + lane);   // hoisted (invariant)
        for (int it = 0; it < 16; ++it) {
            int c = it * 8 + warp;
            float dc = dinv[c];
            float acc = bias_l + dc * dc * XW[c * 36 + lane];
            #pragma unroll
            for (int k = 0; k < 8; ++k) {
                int r = rows8[c * 8 + k];
                acc = fmaf(dinv[r] * dc, XW[r * 36 + lane], acc);
            }
            if (c == li)      acc = fmaf(dinv[lj] * dc, XW[lj * 36 + lane], acc);
            else if (c == lj) acc = fmaf(dinv[li] * dc, XW[li * 36 + lane], acc);
            X[c * 36 + lane] = (l < 2) ? fmaxf(acc, 0.f) : acc;
        }
        stsW(Wb, tid, wreg);
        __syncthreads();
    }

    // Attention projections (prefetch-next between phases)
    wreg = ldgW(k2_W, 64, 0, tid);
    gemm_tile(X, Wb, k1_b, XW, 36, tid, 1);
    __syncthreads();
    stsW(Wb, tid, wreg);  __syncthreads();
    wreg = ldgW(k2_W, 64, 32, tid);
    gemm_tile(XW, Wb, k2_b, Q2, 68, tid, 0);
    __syncthreads();
    stsW(Wb, tid, wreg);  __syncthreads();
    wreg = ldgW(q1_W, 32, 0, tid);
    gemm_tile(XW, Wb, k2_b + 32, Q2 + 32, 68, tid, 0);
    __syncthreads();
    stsW(Wb, tid, wreg);  __syncthreads();
    wreg = ldgW(q2_W, 64, 0, tid);
    gemm_tile(X, Wb, q1_b, XW, 36, tid, 1);
    __syncthreads();
    stsW(Wb, tid, wreg);  __syncthreads();
    wreg = ldgW(q2_W, 64, 32, tid);
    gemm_tile(XW, Wb, q2_b, K2, 68, tid, 0);
    __syncthreads();
    stsW(Wb, tid, wreg);  __syncthreads();
    gemm_tile(XW, Wb, q2_b + 32, K2 + 32, 68, tid, 0);
    __syncthreads();

    // Attention per (col c, head h): float4 dots, segment softmax -> compact rep
    const int c = tid & 127;
    const int h = tid >> 7;
    const float isq = 0.17677669529663687f;

    float4 kv4[8];
    {
        const float4* kr = (const float4*)(K2 + c * 68 + h * 32);
        #pragma unroll
        for (int u = 0; u < 8; ++u) kv4[u] = kr[u];
    }

    float w[8];
    int rws[8];
    #pragma unroll
    for (int k = 0; k < 8; ++k) {
        int r = rows8[c * 8 + k];
        rws[k] = r;
        const float4* qr = (const float4*)(Q2 + r * 68 + h * 32);
        float s = 0.f;
        #pragma unroll
        for (int u = 0; u < 8; ++u) {
            float4 q = qr[u];
            s = fmaf(q.x, kv4[u].x, s); s = fmaf(q.y, kv4[u].y, s);
            s = fmaf(q.z, kv4[u].z, s); s = fmaf(q.w, kv4[u].w, s);
        }
        w[k] = s * isq;
    }
    bool cand = (c == li) || (c == lj);
    float w8 = 0.f;
    if (cand) {
        int r = (c == li) ? lj : li;
        const float4* qr = (const float4*)(Q2 + r * 68 + h * 32);
        float s = 0.f;
        #pragma unroll
        for (int u = 0; u < 8; ++u) {
            float4 q = qr[u];
            s = fmaf(q.x, kv4[u].x, s); s = fmaf(q.y, kv4[u].y, s);
            s = fmaf(q.z, kv4[u].z, s); s = fmaf(q.w, kv4[u].w, s);
        }
        w8 = s * isq;
        wcs[h * 2 + (c == li ? 1 : 0)] = 1.f / (1.f + expf(-w8));
    }
    float wmax = w[0];
    #pragma unroll
    for (int k = 1; k < 8; ++k) wmax = fmaxf(wmax, w[k]);
    if (cand) wmax = fmaxf(wmax, w8);

    float ews[8];
    float sum8 = 0.f;
    #pragma unroll
    for (int k = 0; k < 8; ++k) { ews[k] = expf(w[k] - wmax); sum8 += ews[k]; }
    float ec = cand ? expf(w8 - wmax) : 0.f;
    float invp = 1.f / (sum8 + ec + 1e-16f);
    float invm = 1.f / (sum8 + 1e-16f);

    size_t vb = (((size_t)h * 256 + b) * 128 + c) * 12;
    *(float4*)(g_vals + vb)     = make_float4(ews[0], ews[1], ews[2], ews[3]);
    *(float4*)(g_vals + vb + 4) = make_float4(ews[4], ews[5], ews[6], ews[7]);
    *(float4*)(g_vals + vb + 8) = make_float4(ec, invp, invm, 0.f);
    if (h == 0) {
        uint2 pk;
        pk.x = (unsigned)rws[0] | ((unsigned)rws[1] << 8) | ((unsigned)rws[2] << 16) | ((unsigned)rws[3] << 24);
        pk.y = (unsigned)rws[4] | ((unsigned)rws[5] << 8) | ((unsigned)rws[6] << 16) | ((unsigned)rws[7] << 24);
        g_rows[b * 128 + c] = pk;
    }
    __syncthreads();
    if (tid < 2) g_omega[b * 2 + tid] = wcs[tid * 2] + wcs[tid * 2 + 1];
}

// ============================================================================
// Kernel 2: per-(h,b) m-chain (512 CTAs). Densify + 3 spsteps (101.4us config).
// ============================================================================
#define CT 1024
#define SMC_FLOATS 36128

__device__ __forceinline__ float wred(float v) {
    #pragma unroll
    for (int off = 16; off; off >>= 1) v += __shfl_down_sync(0xffffffffu, v, off);
    return v;
}

__device__ __forceinline__ void spstep(const float* __restrict__ In, float* __restrict__ Out,
                                       const float* __restrict__ sv, const int* __restrict__ sr,
                                       int warp, int lane) {
    const float4* In4 = (const float4*)In;
    #pragma unroll
    for (int it = 0; it < 4; ++it) {
        int c = it * 32 + warp;
        float v[8]; int r[8];
        #pragma unroll
        for (int k = 0; k < 8; ++k) { v[k] = sv[c * 10 + k]; r[k] = sr[c * 10 + k]; }
        float4 acc = make_float4(0.f, 0.f, 0.f, 0.f);
        #pragma unroll
        for (int k = 0; k < 8; ++k) {
            float4 x = In4[r[k] * 32 + lane];
            acc.x = fmaf(v[k], x.x, acc.x);
            acc.y = fmaf(v[k], x.y, acc.y);
            acc.z = fmaf(v[k], x.z, acc.z);
            acc.w = fmaf(v[k], x.w, acc.w);
        }
        *(float4*)(Out + c * 128 + lane * 4) = acc;
    }
}

__global__ __launch_bounds__(CT) void chain_kernel(const int* __restrict__ node_i,
                                                   const int* __restrict__ node_j) {
    extern __shared__ float sm[];
    float* A    = sm;            // T2, later T4
    float* Bm   = sm + 16384;    // T_dense, then T3
    float* sv   = sm + 32768;    // [128][10] (8 used)
    int*   sr   = (int*)(sm + 34048);
    float* colb = sm + 35328;    // 4 x 128
    float* part = sm + 35840;    // [7][32]
    float* res  = sm + 36064;    // 16 (t2..t8)
    float* ent  = sm + 36080;    // [9][4] {ii,ij,ji,jj}

    const int tid  = threadIdx.x;
    const int bid  = blockIdx.x;
    const int h    = bid >> 8;
    const int b    = bid & 255;
    const int li   = node_i[b] - b * 128;
    const int lj   = node_j[b] - b * 128;
    const int warp = tid >> 5, lane = tid & 31;

    if (tid < 128) {
        int c = tid;
        uint2 pr = g_rows[b * 128 + c];
        const float4* gv = (const float4*)(g_vals + (((size_t)h * 256 + b) * 128 + c) * 12);
        float4 v0 = gv[0], v1 = gv[1], v2 = gv[2];
        float inv = v2.z;   // invm
        float ev[8] = {v0.x, v0.y, v0.z, v0.w, v1.x, v1.y, v1.z, v1.w};
        #pragma unroll
        for (int k = 0; k < 4; ++k) {
            sr[c * 10 + k]     = (pr.x >> (8 * k)) & 255;
            sr[c * 10 + 4 + k] = (pr.y >> (8 * k)) & 255;
        }
        #pragma unroll
        for (int k = 0; k < 8; ++k) sv[c * 10 + k] = ev[k] * inv;
    }
    for (int i = tid; i < 4096; i += CT)
        *(float4*)(Bm + i * 4) = make_float4(0.f, 0.f, 0.f, 0.f);
    __syncthreads();                                              // (1)

    // densify T into Bm: one atomic per (row, slot)
    {
        int c = tid >> 3, k = tid & 7;
        atomicAdd(&Bm[c * 128 + sr[c * 10 + k]], sv[c * 10 + k]);
    }
    __syncthreads();                                              // (2)

    spstep(Bm, A, sv, sr, warp, lane);   // A = T * T_dense = T2
    __syncthreads();                                              // (3)

    // phase A: t2 partials, ent[0..2]; then T3 = T*T2 (overwrites T_dense)
    {
        float p = (lane < 4) ? A[(4 * warp + lane) * 129] : 0.f;
        p = wred(p);
        if (lane == 0) part[warp] = p;
        if (warp == 31 && lane == 0) {
            ent[8]  = A[li * 129];        ent[9]  = A[li * 128 + lj];
            ent[10] = A[lj * 128 + li];   ent[11] = A[lj * 129];
        }
        if (warp == 28 && lane == 0) { ent[0] = 1.f; ent[1] = 0.f; ent[2] = 0.f; ent[3] = 1.f; }
        if (warp == 29 && lane < 2) {
            int u = lane ? lj : li;
            float eu = 0.f, ev_ = 0.f;
            #pragma unroll
            for (int k = 0; k < 8; ++k) {
                int r = sr[u * 10 + k];
                float v = sv[u * 10 + k];
                if (r == li) eu += v;
                if (r == lj) ev_ += v;
            }
            ent[4 + 2 * lane] = eu;
            ent[5 + 2 * lane] = ev_;
        }
    }
    spstep(A, Bm, sv, sr, warp, lane);
    __syncthreads();                                              // (4)

    // phase B: t3 partials + ent[3]; then T4 = T*T3 (overwrites T2)
    {
        float p = (lane < 4) ? Bm[(4 * warp + lane) * 129] : 0.f;
        p = wred(p);
        if (lane == 0) part[32 + warp] = p;
        if (warp == 31 && lane == 0) {
            ent[12] = Bm[li * 129];       ent[13] = Bm[li * 128 + lj];
            ent[14] = Bm[lj * 128 + li];  ent[15] = Bm[lj * 129];
        }
    }
    spstep(Bm, A, sv, sr, warp, lane);
    __syncthreads();                                              // (5)

    // phase C: t4/t5 partials, walk, ent[4..5], columns
    {
        float p4 = (lane < 4) ? A[(4 * warp + lane) * 129] : 0.f;
        float p5 = 0.f;
        if (lane < 4) {
            int rw = 4 * warp + lane;
            #pragma unroll
            for (int k = 0; k < 8; ++k)
                p5 = fmaf(sv[rw * 10 + k], A[sr[rw * 10 + k] * 128 + rw], p5);
        }
        float t6 = 0.f, t7 = 0.f, t8 = 0.f;
        for (int g = tid; g < 8064; g += CT) {
            int d = (g >> 7) + 1;
            int a = g & 127;
            int y = (a + d) & 127;
            float x3ab = Bm[a * 128 + y], x3ba = Bm[y * 128 + a];
            float x4ab = A[a * 128 + y],  x4ba = A[y * 128 + a];
            t6 = fmaf(2.f * x3ab, x3ba, t6);
            t7 = fmaf(x3ab, x4ba, fmaf(x3ba, x4ab, t7));
            t8 = fmaf(2.f * x4ab, x4ba, t8);
        }
        if (tid < 64) {
            int a = tid, y = a + 64;
            float x3ab = Bm[a * 128 + y], x3ba = Bm[y * 128 + a];
            float x4ab = A[a * 128 + y],  x4ba = A[y * 128 + a];
            t6 = fmaf(2.f * x3ab, x3ba, t6);
            t7 = fmaf(x3ab, x4ba, fmaf(x3ba, x4ab, t7));
            t8 = fmaf(2.f * x4ab, x4ba, t8);
        }
        if (tid < 128) {
            float d3 = Bm[tid * 129], d4 = A[tid * 129];
            t6 = fmaf(d3, d3, t6);
            t7 = fmaf(d3, d4, t7);
            t8 = fmaf(d4, d4, t8);
        }
        p4 = wred(p4); p5 = wred(p5);
        t6 = wred(t6); t7 = wred(t7); t8 = wred(t8);
        if (lane == 0) {
            part[2 * 32 + warp] = p4;
            part[3 * 32 + warp] = p5;
            part[4 * 32 + warp] = t6;
            part[5 * 32 + warp] = t7;
            part[6 * 32 + warp] = t8;
        }
        if (warp == 31 && lane == 0) {
            ent[16] = A[li * 129];        ent[17] = A[li * 128 + lj];
            ent[18] = A[lj * 128 + li];   ent[19] = A[lj * 129];
        }
        if (warp == 30 && lane < 4) {
            int u = (lane < 2) ? li : lj;
            int v = (lane & 1) ? lj : li;
            float s = 0.f;
            #pragma unroll
            for (int k = 0; k < 8; ++k)
                s = fmaf(sv[u * 10 + k], A[sr[u * 10 + k] * 128 + v], s);
            ent[20 + lane] = s;
        }
        if (tid >= 512) {
            int t = tid - 512;
            int w = t >> 7, m = t & 127;
            const float* M = (w < 2) ? Bm : A;
            int v = (w & 1) ? lj : li;
            colb[w * 128 + m] = M[m * 128 + v];
        }
    }
    __syncthreads();                                              // (6)

    // phase D: 12 dots -> ent[6..8]; final trace reductions -> res[0..6]
    if (warp < 12) {
        const float* R; int u; const float* C;
        if (warp < 4)      { R = Bm; u = (warp < 2) ? li : lj; C = colb + (warp & 1) * 128; }
        else if (warp < 8) { R = Bm; u = (warp < 6) ? li : lj; C = colb + (2 + (warp & 1)) * 128; }
        else               { R = A;  u = (warp < 10) ? li : lj; C = colb + (2 + (warp & 1)) * 128; }
        float s = 0.f;
        #pragma unroll
        for (int q = 0; q < 4; ++q) { int m = lane + 32 * q; s = fmaf(R[u * 128 + m], C[m], s); }
        s = wred(s);
        if (lane == 0) ent[(6 + (warp >> 2)) * 4 + (warp & 3)] = s;
    }
    if (warp >= 16 && warp < 23) {
        float s = part[(warp - 16) * 32 + lane];
        s = wred(s);
        if (lane == 0) res[warp - 16] = s;
    }
    __syncthreads();                                              // (7)

    const size_t mc = (size_t)(2 + h) * 256 + b;
    if (tid < 7)       g_feats[mc * 21 + tid] = res[tid];
    else if (tid < 14) { int k = tid - 7 + 2;  g_feats[mc * 21 + tid] = ent[k * 4] + ent[k * 4 + 3]; }
    else if (tid < 21) { int k = tid - 14 + 2; g_feats[mc * 21 + tid] = ent[k * 4 + 1] + ent[k * 4 + 2]; }
    else if (tid < 57) g_ent[((size_t)h * 256 + b) * 36 + tid - 21] = ent[tid - 21];
}

// ============================================================================
// Kernel 3: warp-per-batch MLP (32 blocks x 256 threads); register DP.
// ============================================================================
__global__ __launch_bounds__(256) void mlp_kernel(
    const float* __restrict__ W1, const float* __restrict__ b1,
    const float* __restrict__ W2, const float* __restrict__ b2,
    const int* __restrict__ node_i, const int* __restrict__ node_j,
    float* __restrict__ out) {
    const int wp = threadIdx.x >> 5;
    const int t  = threadIdx.x & 31;
    const int b  = blockIdx.x * 8 + wp;
    __shared__ float feat[8][72];
    __shared__ float mf[8][2][21];
    __shared__ float entS[8][2][36];
    __shared__ float pf[8][2][21];

    for (int q = t; q < 42; q += 32) mf[wp][q / 21][q % 21] = g_feats[((size_t)(2 + q / 21) * 256 + b) * 21 + q % 21];
    for (int q = t; q < 72; q += 32) entS[wp][q / 36][q % 36] = g_ent[((size_t)(q / 36) * 256 + b) * 36 + q % 36];
    __syncwarp();

    if (t == 0 || t == 16) {
        const int h = t >> 4;
        float E[36], G[32], Wp[32], Wn[32], Xc[36], tc[9];
        #pragma unroll
        for (int q = 0; q < 36; ++q) E[q] = entS[wp][h][q];
        const int li = node_i[b] - b * 128;
        const int lj = node_j[b] - b * 128;
        const float* gvi = g_vals + (((size_t)h * 256 + b) * 128 + li) * 12 + 8;
        const float* gvj = g_vals + (((size_t)h * 256 + b) * 128 + lj) * 12 + 8;
        float ai = gvi[1] / gvi[2], bi = gvi[0] * gvi[1];
        float aj = gvj[1] / gvj[2], bj = gvj[0] * gvj[1];

        #pragma unroll
        for (int a = 0; a < 8; ++a) {
            G[a * 4 + 0] = (ai - 1.f) * E[(a + 1) * 4 + 0] + bi * E[a * 4 + 2];
            G[a * 4 + 1] = (ai - 1.f) * E[(a + 1) * 4 + 1] + bi * E[a * 4 + 3];
            G[a * 4 + 2] = (aj - 1.f) * E[(a + 1) * 4 + 2] + bj * E[a * 4 + 0];
            G[a * 4 + 3] = (aj - 1.f) * E[(a + 1) * 4 + 3] + bj * E[a * 4 + 1];
        }
        #pragma unroll
        for (int k = 0; k < 9; ++k) {
            tc[k] = 0.f;
            Xc[k * 4] = 0.f; Xc[k * 4 + 1] = 0.f; Xc[k * 4 + 2] = 0.f; Xc[k * 4 + 3] = 0.f;
        }
        #pragma unroll
        for (int a = 0; a < 8; ++a) {
            Wp[a * 4 + 0] = G[a * 4 + 0]; Wp[a * 4 + 1] = G[a * 4 + 1];
            Wp[a * 4 + 2] = G[a * 4 + 2]; Wp[a * 4 + 3] = G[a * 4 + 3];
            tc[a + 1] += G[a * 4 + 0] + G[a * 4 + 3];
        }
        #pragma unroll
        for (int bb = 0; bb < 8; ++bb) {
            float t0 = E[bb * 4 + 0] * G[0] + E[bb * 4 + 1] * G[2];
            float t1 = E[bb * 4 + 0] * G[1] + E[bb * 4 + 1] * G[3];
            float t2 = E[bb * 4 + 2] * G[0] + E[bb * 4 + 3] * G[2];
            float t3 = E[bb * 4 + 2] * G[1] + E[bb * 4 + 3] * G[3];
            Xc[(bb + 1) * 4 + 0] += t0; Xc[(bb + 1) * 4 + 1] += t1;
            Xc[(bb + 1) * 4 + 2] += t2; Xc[(bb + 1) * 4 + 3] += t3;
        }
        #pragma unroll
        for (int c = 1; c < 8; ++c) {
            #pragma unroll
            for (int a = 0; a < 8; ++a) {
                if (a <= 7 - c) {
                    float t0 = Wp[0] * G[a * 4 + 0] + Wp[1] * G[a * 4 + 2];
                    float t1 = Wp[0] * G[a * 4 + 1] + Wp[1] * G[a * 4 + 3];
                    float t2 = Wp[2] * G[a * 4 + 0] + Wp[3] * G[a * 4 + 2];
                    float t3 = Wp[2] * G[a * 4 + 1] + Wp[3] * G[a * 4 + 3];
                    Wn[a * 4 + 0] = Wp[(a + 1) * 4 + 0] + t0;
                    Wn[a * 4 + 1] = Wp[(a + 1) * 4 + 1] + t1;
                    Wn[a * 4 + 2] = Wp[(a + 1) * 4 + 2] + t2;
                    Wn[a * 4 + 3] = Wp[(a + 1) * 4 + 3] + t3;
                    tc[a + c + 1] += Wn[a * 4 + 0] + Wn[a * 4 + 3];
                }
            }
            #pragma unroll
            for (int bb = 0; bb < 8; ++bb) {
                if (bb <= 7 - c) {
                    float t0 = E[bb * 4 + 0] * Wn[0] + E[bb * 4 + 1] * Wn[2];
                    float t1 = E[bb * 4 + 0] * Wn[1] + E[bb * 4 + 1] * Wn[3];
                    float t2 = E[bb * 4 + 2] * Wn[0] + E[bb * 4 + 3] * Wn[2];
                    float t3 = E[bb * 4 + 2] * Wn[1] + E[bb * 4 + 3] * Wn[3];
                    Xc[(bb + c + 1) * 4 + 0] += t0; Xc[(bb + c + 1) * 4 + 1] += t1;
                    Xc[(bb + c + 1) * 4 + 2] += t2; Xc[(bb + c + 1) * 4 + 3] += t3;
                }
            }
            #pragma unroll
            for (int a = 0; a < 8; ++a) {
                if (a <= 7 - c) {
                    Wp[a * 4 + 0] = Wn[a * 4 + 0]; Wp[a * 4 + 1] = Wn[a * 4 + 1];
                    Wp[a * 4 + 2] = Wn[a * 4 + 2]; Wp[a * 4 + 3] = Wn[a * 4 + 3];
                }
            }
        }
        #pragma unroll
        for (int k = 2; k <= 8; ++k) {
            pf[wp][h][k - 2]      = mf[wp][h][k - 2] + tc[k];
            pf[wp][h][7 + k - 2]  = E[k * 4 + 0] + E[k * 4 + 3] + Xc[k * 4 + 0] + Xc[k * 4 + 3];
            pf[wp][h][14 + k - 2] = E[k * 4 + 1] + E[k * 4 + 2] + Xc[k * 4 + 1] + Xc[k * 4 + 2];
        }
    }
    __syncwarp();

    for (int s = t; s < 72; s += 32) {
        float v;
        if (s < 14) {
            int h = s / 7, k = s % 7;
            v = pf[wp][h][k] - mf[wp][h][k];
        } else if (s < 16) {
            v = g_omega[b * 2 + (s - 14)];
        } else {
            int m = (s - 16) % 14;
            int blk = (s - 16) / 14;
            int h = m / 7, k = m % 7;
            if (blk == 0)      v = pf[wp][h][7 + k];
            else if (blk == 1) v = mf[wp][h][7 + k];
            else if (blk == 2) v = pf[wp][h][14 + k];
            else               v = mf[wp][h][14 + k];
        }
        feat[wp][s] = v;
    }
    __syncwarp();

    float h1 = b1[t];
    #pragma unroll 8
    for (int m = 0; m < 72; ++m) h1 = fmaf(feat[wp][m], W1[m * 32 + t], h1);
    h1 = fmaxf(h1, 0.f);
    float v = h1 * W2[t];
    #pragma unroll
    for (int off = 16; off; off >>= 1) v += __shfl_down_sync(0xffffffffu, v, off);
    if (t == 0) out[b] = v + b2[0];
}

// ============================================================================
extern "C" void kernel_launch(void* const* d_in, const int* in_sizes, int n_in,
                              void* d_out, int out_size) {
    (void)in_sizes; (void)n_in; (void)out_size;
    const float* z_table = (const float*)d_in[0];
    const float* conv_W  = (const float*)d_in[1];
    const float* conv_b  = (const float*)d_in[2];
    const float* k1_W    = (const float*)d_in[3];
    const float* k1_b    = (const float*)d_in[4];
    const float* q1_W    = (const float*)d_in[5];
    const float* q1_b    = (const float*)d_in[6];
    const float* k2_W    = (const float*)d_in[7];
    const float* k2_b    = (const float*)d_in[8];
    const float* q2_W    = (const float*)d_in[9];
    const float* q2_b    = (const float*)d_in[10];
    const float* mlp_W1  = (const float*)d_in[11];
    const float* mlp_b1  = (const float*)d_in[12];
    const float* mlp_W2  = (const float*)d_in[13];
    const float* mlp_b2  = (const float*)d_in[14];
    const int*   z        = (const int*)d_in[15];
    const int*   edge_row = (const int*)d_in[16];
    const int*   node_i   = (const int*)d_in[20];
    const int*   node_j   = (const int*)d_in[21];
    float* out = (float*)d_out;

    cudaFuncSetAttribute(batch_kernel, cudaFuncAttributeMaxDynamicSharedMemorySize, SMB_FLOATS * 4);
    cudaFuncSetAttribute(chain_kernel, cudaFuncAttributeMaxDynamicSharedMemorySize, SMC_FLOATS * 4);

    batch_kernel<<<NB, 256, SMB_FLOATS * 4>>>(
        z_table, conv_W, conv_b, k1_W, k1_b, q1_W, q1_b,
        k2_W, k2_b, q2_W, q2_b, z, edge_row, node_i, node_j);
    chain_kernel<<<2 * NB, CT, SMC_FLOATS * 4>>>(node_i, node_j);
    mlp_kernel<<<32, 256>>>(mlp_W1, mlp_b1, mlp_W2, mlp_b2, node_i, node_j, out);
}